// round 1
// baseline (speedup 1.0000x reference)
#include <cuda_runtime.h>

// ----------------------------------------------------------------------------
// MMDecoderLSTM: 30-step LSTM (H=64, EMB=16) over B=131072 elements.
// One thread per batch element. Weights in shared memory (broadcast reads).
// Dot products use Blackwell packed fp32x2 FMA (fma.rn.f32x2) for 2x FLOP rate.
//
// Algebraic fusion: x_{t+1} = leaky_relu( h_t @ (W_se@W_h2p)^T + (W_se@b_h2p + b_se) )
// so the two chained heads become one 16x64 GEMV (W_comb) per step.
// ----------------------------------------------------------------------------

#define SEQ_LEN 30
#define HDIM    64
#define EMB     16

typedef unsigned long long u64;

// Precomputed (setup kernel) combined weights
__device__ float g_wcomb[EMB * HDIM];   // W_se @ W_h2p  (16 x 64)
__device__ float g_bcomb[EMB];          // W_se @ b_h2p + b_se
__device__ float g_bias[4 * HDIM];      // b_ih + b_hh
__device__ float g_wsex[EMB];           // W_se[:,0]+W_se[:,2]+W_se[:,4]
__device__ float g_wsey[EMB];           // W_se[:,1]+W_se[:,3]+W_se[:,5]

__global__ void setup_kernel(const float* __restrict__ W_se,
                             const float* __restrict__ b_se,
                             const float* __restrict__ W_h2p,
                             const float* __restrict__ b_h2p,
                             const float* __restrict__ b_ih,
                             const float* __restrict__ b_hh) {
    int t = threadIdx.x;
    for (int idx = t; idx < EMB * HDIM; idx += blockDim.x) {
        int i = idx >> 6, j = idx & 63;
        float s = 0.f;
#pragma unroll
        for (int p = 0; p < 6; p++) s += W_se[i * 6 + p] * W_h2p[p * HDIM + j];
        g_wcomb[idx] = s;
    }
    if (t < EMB) {
        float s = 0.f;
#pragma unroll
        for (int p = 0; p < 6; p++) s += W_se[t * 6 + p] * b_h2p[p];
        g_bcomb[t] = s + b_se[t];
        g_wsex[t] = W_se[t * 6 + 0] + W_se[t * 6 + 2] + W_se[t * 6 + 4];
        g_wsey[t] = W_se[t * 6 + 1] + W_se[t * 6 + 3] + W_se[t * 6 + 5];
    }
    if (t < 4 * HDIM) g_bias[t] = b_ih[t] + b_hh[t];
}

// ---- packed fp32x2 helpers (Blackwell sm_100+) ----
__device__ __forceinline__ void fma2(u64& acc, u64 a, u64 b) {
    asm("fma.rn.f32x2 %0, %1, %2, %0;" : "+l"(acc) : "l"(a), "l"(b));
}
__device__ __forceinline__ float hadd2(u64 v) {
    float lo, hi;
    asm("mov.b64 {%0, %1}, %2;" : "=f"(lo), "=f"(hi) : "l"(v));
    return lo + hi;
}
__device__ __forceinline__ u64 pack2(float lo, float hi) {
    u64 v;
    asm("mov.b64 %0, {%1, %2};" : "=l"(v) : "f"(lo), "f"(hi));
    return v;
}

__device__ __forceinline__ float fast_sigmoid(float v) {
    float e = __expf(-v);
    return __fdividef(1.f, 1.f + e);
}
__device__ __forceinline__ float fast_tanh(float v) {
    float e = __expf(-2.f * v);
    return __fdividef(2.f, 1.f + e) - 1.f;
}
__device__ __forceinline__ float leaky(float v) {
    return fmaxf(v, 0.f) + 0.01f * fminf(v, 0.f);
}

// shared memory layout (in floats)
#define OFF_WHH   0                      // 256*64 = 16384
#define OFF_WIH   16384                  // 256*16 = 4096
#define OFF_WCOMB 20480                  // 16*64  = 1024
#define OFF_WH2P  21504                  // 6*64   = 384
#define OFF_WCONF 21888                  // 3*64   = 192
#define OFF_BIAS  22080                  // 256
#define OFF_BH2P  22336                  // 8 (6 used)
#define OFF_BCOMB 22344                  // 16
#define OFF_WSEX  22360                  // 16
#define OFF_WSEY  22376                  // 16
#define OFF_BSE   22392                  // 16
#define OFF_BCONF 22408                  // 8 (3 used)
#define SMEM_FLOATS 22416
#define SMEM_BYTES (SMEM_FLOATS * 4)

__global__ void __launch_bounds__(128)
lstm_kernel(const float* __restrict__ traj_rel,
            const float* __restrict__ h0, const float* __restrict__ c0,
            const float* __restrict__ W_ih, const float* __restrict__ W_hh,
            const float* __restrict__ W_h2p, const float* __restrict__ b_h2p,
            const float* __restrict__ b_se,
            const float* __restrict__ W_conf, const float* __restrict__ b_conf,
            float* __restrict__ out, int batch) {
    extern __shared__ float sm[];
    int tid = threadIdx.x;

    // ---- stage weights into shared memory ----
    for (int i = tid; i < 16384; i += 128) sm[OFF_WHH + i] = W_hh[i];
    for (int i = tid; i < 4096; i += 128)  sm[OFF_WIH + i] = W_ih[i];
    for (int i = tid; i < 1024; i += 128)  sm[OFF_WCOMB + i] = g_wcomb[i];
    for (int i = tid; i < 384; i += 128)   sm[OFF_WH2P + i] = W_h2p[i];
    for (int i = tid; i < 192; i += 128)   sm[OFF_WCONF + i] = W_conf[i];
    for (int i = tid; i < 256; i += 128)   sm[OFF_BIAS + i] = g_bias[i];
    if (tid < 6)  sm[OFF_BH2P + tid] = b_h2p[tid];
    if (tid < 16) {
        sm[OFF_BCOMB + tid] = g_bcomb[tid];
        sm[OFF_WSEX + tid]  = g_wsex[tid];
        sm[OFF_WSEY + tid]  = g_wsey[tid];
        sm[OFF_BSE + tid]   = b_se[tid];
    }
    if (tid < 3)  sm[OFF_BCONF + tid] = b_conf[tid];
    __syncthreads();

    int b = blockIdx.x * 128 + tid;
    if (b >= batch) return;

    const ulonglong2* WhhV   = reinterpret_cast<const ulonglong2*>(sm + OFF_WHH);
    const ulonglong2* WihV   = reinterpret_cast<const ulonglong2*>(sm + OFF_WIH);
    const ulonglong2* WcombV = reinterpret_cast<const ulonglong2*>(sm + OFF_WCOMB);
    const ulonglong2* Wh2pV  = reinterpret_cast<const ulonglong2*>(sm + OFF_WH2P);
    const ulonglong2* WconfV = reinterpret_cast<const ulonglong2*>(sm + OFF_WCONF);
    const float* sBias  = sm + OFF_BIAS;
    const float* sBh2p  = sm + OFF_BH2P;
    const float* sBcomb = sm + OFF_BCOMB;

    // ---- load h0 (packed pairs, registers) and c0 (local) ----
    u64 h2[32];
    {
        const ulonglong2* ph = reinterpret_cast<const ulonglong2*>(h0) + (size_t)b * 16;
#pragma unroll
        for (int j = 0; j < 16; j++) {
            ulonglong2 v = ph[j];
            h2[2 * j] = v.x;
            h2[2 * j + 1] = v.y;
        }
    }
    float cl[HDIM];   // local memory (dynamic index in k loop) — coalesced per warp
    float hn[HDIM];
    {
        const float4* pc = reinterpret_cast<const float4*>(c0) + (size_t)b * 16;
        for (int j = 0; j < 16; j++) {
            float4 v = pc[j];
            cl[4 * j] = v.x; cl[4 * j + 1] = v.y; cl[4 * j + 2] = v.z; cl[4 * j + 3] = v.w;
        }
    }

    // ---- initial x = leaky(traj6 @ W_se^T + b_se), traj6 = tile([tx,ty],3) ----
    u64 xp[8];
    {
        float tx = traj_rel[(size_t)b * 2 + 0];
        float ty = traj_rel[(size_t)b * 2 + 1];
#pragma unroll
        for (int i = 0; i < 8; i++) {
            float a0 = leaky(tx * sm[OFF_WSEX + 2 * i]     + ty * sm[OFF_WSEY + 2 * i]     + sm[OFF_BSE + 2 * i]);
            float a1 = leaky(tx * sm[OFF_WSEX + 2 * i + 1] + ty * sm[OFF_WSEY + 2 * i + 1] + sm[OFF_BSE + 2 * i + 1]);
            xp[i] = pack2(a0, a1);
        }
    }

    float* outp = out + (size_t)b * (3 * SEQ_LEN * 2);

#pragma unroll 1
    for (int t = 0; t < SEQ_LEN; t++) {
        // ---- gates: 256 x (16 + 64) GEMV, 4 gates per k with packed FMA ----
#pragma unroll 1
        for (int k = 0; k < HDIM; k++) {
            u64 ai = 0, af = 0, ag = 0, ao = 0;
            const ulonglong2* wi = WihV + k * 4;
            const ulonglong2* wf = WihV + (64 + k) * 4;
            const ulonglong2* wg = WihV + (128 + k) * 4;
            const ulonglong2* wo = WihV + (192 + k) * 4;
#pragma unroll
            for (int j = 0; j < 4; j++) {
                ulonglong2 w;
                w = wi[j]; fma2(ai, w.x, xp[2 * j]); fma2(ai, w.y, xp[2 * j + 1]);
                w = wf[j]; fma2(af, w.x, xp[2 * j]); fma2(af, w.y, xp[2 * j + 1]);
                w = wg[j]; fma2(ag, w.x, xp[2 * j]); fma2(ag, w.y, xp[2 * j + 1]);
                w = wo[j]; fma2(ao, w.x, xp[2 * j]); fma2(ao, w.y, xp[2 * j + 1]);
            }
            const ulonglong2* hi_ = WhhV + k * 16;
            const ulonglong2* hf_ = WhhV + (64 + k) * 16;
            const ulonglong2* hg_ = WhhV + (128 + k) * 16;
            const ulonglong2* ho_ = WhhV + (192 + k) * 16;
#pragma unroll
            for (int j = 0; j < 16; j++) {
                ulonglong2 w;
                w = hi_[j]; fma2(ai, w.x, h2[2 * j]); fma2(ai, w.y, h2[2 * j + 1]);
                w = hf_[j]; fma2(af, w.x, h2[2 * j]); fma2(af, w.y, h2[2 * j + 1]);
                w = hg_[j]; fma2(ag, w.x, h2[2 * j]); fma2(ag, w.y, h2[2 * j + 1]);
                w = ho_[j]; fma2(ao, w.x, h2[2 * j]); fma2(ao, w.y, h2[2 * j + 1]);
            }
            float gi = hadd2(ai) + sBias[k];
            float gf = hadd2(af) + sBias[64 + k];
            float gg = hadd2(ag) + sBias[128 + k];
            float go = hadd2(ao) + sBias[192 + k];
            float iv = fast_sigmoid(gi);
            float fv = fast_sigmoid(gf);
            float gv = fast_tanh(gg);
            float ov = fast_sigmoid(go);
            float cc = fv * cl[k] + iv * gv;
            cl[k] = cc;
            hn[k] = ov * fast_tanh(cc);
        }

        // ---- commit new h (packed) ----
#pragma unroll
        for (int j = 0; j < 32; j++) h2[j] = pack2(hn[2 * j], hn[2 * j + 1]);

        // ---- rel = h @ W_h2p^T + b_h2p  -> pred output ----
#pragma unroll
        for (int r = 0; r < 6; r++) {
            u64 a = 0;
            const ulonglong2* w = Wh2pV + r * 16;
#pragma unroll
            for (int j = 0; j < 16; j++) {
                ulonglong2 wv = w[j];
                fma2(a, wv.x, h2[2 * j]); fma2(a, wv.y, h2[2 * j + 1]);
            }
            float rel = hadd2(a) + sBh2p[r];
            int s = r >> 1, d = r & 1;
            outp[s * (SEQ_LEN * 2) + t * 2 + d] = rel;
        }

        // ---- x_{t+1} = leaky(h @ W_comb^T + b_comb) ----
#pragma unroll
        for (int i = 0; i < 8; i++) {
            u64 a0 = 0, a1 = 0;
            const ulonglong2* w0 = WcombV + (2 * i) * 16;
            const ulonglong2* w1 = WcombV + (2 * i + 1) * 16;
#pragma unroll
            for (int j = 0; j < 16; j++) {
                ulonglong2 wa = w0[j];
                fma2(a0, wa.x, h2[2 * j]); fma2(a0, wa.y, h2[2 * j + 1]);
                ulonglong2 wb = w1[j];
                fma2(a1, wb.x, h2[2 * j]); fma2(a1, wb.y, h2[2 * j + 1]);
            }
            float x0 = leaky(hadd2(a0) + sBcomb[2 * i]);
            float x1 = leaky(hadd2(a1) + sBcomb[2 * i + 1]);
            xp[i] = pack2(x0, x1);
        }
    }

    // ---- conf = softmax(h_final @ W_conf^T + b_conf) ----
    float lg[3];
#pragma unroll
    for (int r = 0; r < 3; r++) {
        u64 a = 0;
        const ulonglong2* w = WconfV + r * 16;
#pragma unroll
        for (int j = 0; j < 16; j++) {
            ulonglong2 wv = w[j];
            fma2(a, wv.x, h2[2 * j]); fma2(a, wv.y, h2[2 * j + 1]);
        }
        lg[r] = hadd2(a) + sm[OFF_BCONF + r];
    }
    float m = fmaxf(lg[0], fmaxf(lg[1], lg[2]));
    float e0 = __expf(lg[0] - m);
    float e1 = __expf(lg[1] - m);
    float e2 = __expf(lg[2] - m);
    float inv = __fdividef(1.f, e0 + e1 + e2);
    size_t confbase = (size_t)batch * (3 * SEQ_LEN * 2);
    out[confbase + (size_t)b * 3 + 0] = e0 * inv;
    out[confbase + (size_t)b * 3 + 1] = e1 * inv;
    out[confbase + (size_t)b * 3 + 2] = e2 * inv;
}

extern "C" void kernel_launch(void* const* d_in, const int* in_sizes, int n_in,
                              void* d_out, int out_size) {
    // metadata order: traj_abs, traj_rel, h0, c0, W_ih, W_hh, b_ih, b_hh,
    //                 W_se, b_se, W_h2p, b_h2p, W_conf, b_conf
    const float* traj_rel = (const float*)d_in[1];
    const float* h0   = (const float*)d_in[2];
    const float* c0   = (const float*)d_in[3];
    const float* W_ih = (const float*)d_in[4];
    const float* W_hh = (const float*)d_in[5];
    const float* b_ih = (const float*)d_in[6];
    const float* b_hh = (const float*)d_in[7];
    const float* W_se = (const float*)d_in[8];
    const float* b_se = (const float*)d_in[9];
    const float* W_h2p = (const float*)d_in[10];
    const float* b_h2p = (const float*)d_in[11];
    const float* W_conf = (const float*)d_in[12];
    const float* b_conf = (const float*)d_in[13];
    float* out = (float*)d_out;

    int batch = in_sizes[2] / HDIM;   // h0 element count / 64

    setup_kernel<<<1, 256>>>(W_se, b_se, W_h2p, b_h2p, b_ih, b_hh);

    cudaFuncSetAttribute(lstm_kernel, cudaFuncAttributeMaxDynamicSharedMemorySize, SMEM_BYTES);
    int grid = (batch + 127) / 128;
    lstm_kernel<<<grid, 128, SMEM_BYTES>>>(traj_rel, h0, c0, W_ih, W_hh,
                                           W_h2p, b_h2p, b_se, W_conf, b_conf,
                                           out, batch);
}

// round 2
// speedup vs baseline: 1.0001x; 1.0001x over previous
#include <cuda_runtime.h>

// ----------------------------------------------------------------------------
// MMDecoderLSTM: 30-step LSTM (H=64, EMB=16) over B=131072 elements.
// One thread per batch element. Weights in shared memory (broadcast reads).
// Dot products use Blackwell packed fp32x2 FMA (fma.rn.f32x2) for 2x FLOP rate.
//
// Algebraic fusion: x_{t+1} = leaky_relu( h_t @ (W_se@W_h2p)^T + (W_se@b_h2p + b_se) )
// so the two chained heads become one 16x64 GEMV (W_comb) per step.
// ----------------------------------------------------------------------------

#define SEQ_LEN 30
#define HDIM    64
#define EMB     16

typedef unsigned long long u64;

// Precomputed (setup kernel) combined weights
__device__ float g_wcomb[EMB * HDIM];   // W_se @ W_h2p  (16 x 64)
__device__ float g_bcomb[EMB];          // W_se @ b_h2p + b_se
__device__ float g_bias[4 * HDIM];      // b_ih + b_hh
__device__ float g_wsex[EMB];           // W_se[:,0]+W_se[:,2]+W_se[:,4]
__device__ float g_wsey[EMB];           // W_se[:,1]+W_se[:,3]+W_se[:,5]

__global__ void setup_kernel(const float* __restrict__ W_se,
                             const float* __restrict__ b_se,
                             const float* __restrict__ W_h2p,
                             const float* __restrict__ b_h2p,
                             const float* __restrict__ b_ih,
                             const float* __restrict__ b_hh) {
    int t = threadIdx.x;
    for (int idx = t; idx < EMB * HDIM; idx += blockDim.x) {
        int i = idx >> 6, j = idx & 63;
        float s = 0.f;
#pragma unroll
        for (int p = 0; p < 6; p++) s += W_se[i * 6 + p] * W_h2p[p * HDIM + j];
        g_wcomb[idx] = s;
    }
    if (t < EMB) {
        float s = 0.f;
#pragma unroll
        for (int p = 0; p < 6; p++) s += W_se[t * 6 + p] * b_h2p[p];
        g_bcomb[t] = s + b_se[t];
        g_wsex[t] = W_se[t * 6 + 0] + W_se[t * 6 + 2] + W_se[t * 6 + 4];
        g_wsey[t] = W_se[t * 6 + 1] + W_se[t * 6 + 3] + W_se[t * 6 + 5];
    }
    if (t < 4 * HDIM) g_bias[t] = b_ih[t] + b_hh[t];
}

// ---- packed fp32x2 helpers (Blackwell sm_100+) ----
__device__ __forceinline__ void fma2(u64& acc, u64 a, u64 b) {
    asm("fma.rn.f32x2 %0, %1, %2, %0;" : "+l"(acc) : "l"(a), "l"(b));
}
__device__ __forceinline__ float hadd2(u64 v) {
    float lo, hi;
    asm("mov.b64 {%0, %1}, %2;" : "=f"(lo), "=f"(hi) : "l"(v));
    return lo + hi;
}
__device__ __forceinline__ u64 pack2(float lo, float hi) {
    u64 v;
    asm("mov.b64 %0, {%1, %2};" : "=l"(v) : "f"(lo), "f"(hi));
    return v;
}

__device__ __forceinline__ float fast_sigmoid(float v) {
    float e = __expf(-v);
    return __fdividef(1.f, 1.f + e);
}
__device__ __forceinline__ float fast_tanh(float v) {
    float e = __expf(-2.f * v);
    return __fdividef(2.f, 1.f + e) - 1.f;
}
__device__ __forceinline__ float leaky(float v) {
    return fmaxf(v, 0.f) + 0.01f * fminf(v, 0.f);
}

// shared memory layout (in floats)
#define OFF_WHH   0                      // 256*64 = 16384
#define OFF_WIH   16384                  // 256*16 = 4096
#define OFF_WCOMB 20480                  // 16*64  = 1024
#define OFF_WH2P  21504                  // 6*64   = 384
#define OFF_WCONF 21888                  // 3*64   = 192
#define OFF_BIAS  22080                  // 256
#define OFF_BH2P  22336                  // 8 (6 used)
#define OFF_BCOMB 22344                  // 16
#define OFF_WSEX  22360                  // 16
#define OFF_WSEY  22376                  // 16
#define OFF_BSE   22392                  // 16
#define OFF_BCONF 22408                  // 8 (3 used)
#define SMEM_FLOATS 22416
#define SMEM_BYTES (SMEM_FLOATS * 4)

__global__ void __launch_bounds__(128)
lstm_kernel(const float* __restrict__ traj_rel,
            const float* __restrict__ h0, const float* __restrict__ c0,
            const float* __restrict__ W_ih, const float* __restrict__ W_hh,
            const float* __restrict__ W_h2p, const float* __restrict__ b_h2p,
            const float* __restrict__ b_se,
            const float* __restrict__ W_conf, const float* __restrict__ b_conf,
            float* __restrict__ out, int batch) {
    extern __shared__ float sm[];
    int tid = threadIdx.x;

    // ---- stage weights into shared memory ----
    for (int i = tid; i < 16384; i += 128) sm[OFF_WHH + i] = W_hh[i];
    for (int i = tid; i < 4096; i += 128)  sm[OFF_WIH + i] = W_ih[i];
    for (int i = tid; i < 1024; i += 128)  sm[OFF_WCOMB + i] = g_wcomb[i];
    for (int i = tid; i < 384; i += 128)   sm[OFF_WH2P + i] = W_h2p[i];
    for (int i = tid; i < 192; i += 128)   sm[OFF_WCONF + i] = W_conf[i];
    for (int i = tid; i < 256; i += 128)   sm[OFF_BIAS + i] = g_bias[i];
    if (tid < 6)  sm[OFF_BH2P + tid] = b_h2p[tid];
    if (tid < 16) {
        sm[OFF_BCOMB + tid] = g_bcomb[tid];
        sm[OFF_WSEX + tid]  = g_wsex[tid];
        sm[OFF_WSEY + tid]  = g_wsey[tid];
        sm[OFF_BSE + tid]   = b_se[tid];
    }
    if (tid < 3)  sm[OFF_BCONF + tid] = b_conf[tid];
    __syncthreads();

    int b = blockIdx.x * 128 + tid;
    if (b >= batch) return;

    const ulonglong2* WhhV   = reinterpret_cast<const ulonglong2*>(sm + OFF_WHH);
    const ulonglong2* WihV   = reinterpret_cast<const ulonglong2*>(sm + OFF_WIH);
    const ulonglong2* WcombV = reinterpret_cast<const ulonglong2*>(sm + OFF_WCOMB);
    const ulonglong2* Wh2pV  = reinterpret_cast<const ulonglong2*>(sm + OFF_WH2P);
    const ulonglong2* WconfV = reinterpret_cast<const ulonglong2*>(sm + OFF_WCONF);
    const float* sBias  = sm + OFF_BIAS;
    const float* sBh2p  = sm + OFF_BH2P;
    const float* sBcomb = sm + OFF_BCOMB;

    // ---- load h0 (packed pairs, registers) and c0 (local) ----
    u64 h2[32];
    {
        const ulonglong2* ph = reinterpret_cast<const ulonglong2*>(h0) + (size_t)b * 16;
#pragma unroll
        for (int j = 0; j < 16; j++) {
            ulonglong2 v = ph[j];
            h2[2 * j] = v.x;
            h2[2 * j + 1] = v.y;
        }
    }
    float cl[HDIM];   // local memory (dynamic index in k loop) — coalesced per warp
    float hn[HDIM];
    {
        const float4* pc = reinterpret_cast<const float4*>(c0) + (size_t)b * 16;
        for (int j = 0; j < 16; j++) {
            float4 v = pc[j];
            cl[4 * j] = v.x; cl[4 * j + 1] = v.y; cl[4 * j + 2] = v.z; cl[4 * j + 3] = v.w;
        }
    }

    // ---- initial x = leaky(traj6 @ W_se^T + b_se), traj6 = tile([tx,ty],3) ----
    u64 xp[8];
    {
        float tx = traj_rel[(size_t)b * 2 + 0];
        float ty = traj_rel[(size_t)b * 2 + 1];
#pragma unroll
        for (int i = 0; i < 8; i++) {
            float a0 = leaky(tx * sm[OFF_WSEX + 2 * i]     + ty * sm[OFF_WSEY + 2 * i]     + sm[OFF_BSE + 2 * i]);
            float a1 = leaky(tx * sm[OFF_WSEX + 2 * i + 1] + ty * sm[OFF_WSEY + 2 * i + 1] + sm[OFF_BSE + 2 * i + 1]);
            xp[i] = pack2(a0, a1);
        }
    }

    float* outp = out + (size_t)b * (3 * SEQ_LEN * 2);

#pragma unroll 1
    for (int t = 0; t < SEQ_LEN; t++) {
        // ---- gates: 256 x (16 + 64) GEMV, 4 gates per k with packed FMA ----
#pragma unroll 1
        for (int k = 0; k < HDIM; k++) {
            u64 ai = 0, af = 0, ag = 0, ao = 0;
            const ulonglong2* wi = WihV + k * 4;
            const ulonglong2* wf = WihV + (64 + k) * 4;
            const ulonglong2* wg = WihV + (128 + k) * 4;
            const ulonglong2* wo = WihV + (192 + k) * 4;
#pragma unroll
            for (int j = 0; j < 4; j++) {
                ulonglong2 w;
                w = wi[j]; fma2(ai, w.x, xp[2 * j]); fma2(ai, w.y, xp[2 * j + 1]);
                w = wf[j]; fma2(af, w.x, xp[2 * j]); fma2(af, w.y, xp[2 * j + 1]);
                w = wg[j]; fma2(ag, w.x, xp[2 * j]); fma2(ag, w.y, xp[2 * j + 1]);
                w = wo[j]; fma2(ao, w.x, xp[2 * j]); fma2(ao, w.y, xp[2 * j + 1]);
            }
            const ulonglong2* hi_ = WhhV + k * 16;
            const ulonglong2* hf_ = WhhV + (64 + k) * 16;
            const ulonglong2* hg_ = WhhV + (128 + k) * 16;
            const ulonglong2* ho_ = WhhV + (192 + k) * 16;
#pragma unroll
            for (int j = 0; j < 16; j++) {
                ulonglong2 w;
                w = hi_[j]; fma2(ai, w.x, h2[2 * j]); fma2(ai, w.y, h2[2 * j + 1]);
                w = hf_[j]; fma2(af, w.x, h2[2 * j]); fma2(af, w.y, h2[2 * j + 1]);
                w = hg_[j]; fma2(ag, w.x, h2[2 * j]); fma2(ag, w.y, h2[2 * j + 1]);
                w = ho_[j]; fma2(ao, w.x, h2[2 * j]); fma2(ao, w.y, h2[2 * j + 1]);
            }
            float gi = hadd2(ai) + sBias[k];
            float gf = hadd2(af) + sBias[64 + k];
            float gg = hadd2(ag) + sBias[128 + k];
            float go = hadd2(ao) + sBias[192 + k];
            float iv = fast_sigmoid(gi);
            float fv = fast_sigmoid(gf);
            float gv = fast_tanh(gg);
            float ov = fast_sigmoid(go);
            float cc = fv * cl[k] + iv * gv;
            cl[k] = cc;
            hn[k] = ov * fast_tanh(cc);
        }

        // ---- commit new h (packed) ----
#pragma unroll
        for (int j = 0; j < 32; j++) h2[j] = pack2(hn[2 * j], hn[2 * j + 1]);

        // ---- rel = h @ W_h2p^T + b_h2p  -> pred output ----
#pragma unroll
        for (int r = 0; r < 6; r++) {
            u64 a = 0;
            const ulonglong2* w = Wh2pV + r * 16;
#pragma unroll
            for (int j = 0; j < 16; j++) {
                ulonglong2 wv = w[j];
                fma2(a, wv.x, h2[2 * j]); fma2(a, wv.y, h2[2 * j + 1]);
            }
            float rel = hadd2(a) + sBh2p[r];
            int s = r >> 1, d = r & 1;
            outp[s * (SEQ_LEN * 2) + t * 2 + d] = rel;
        }

        // ---- x_{t+1} = leaky(h @ W_comb^T + b_comb) ----
#pragma unroll
        for (int i = 0; i < 8; i++) {
            u64 a0 = 0, a1 = 0;
            const ulonglong2* w0 = WcombV + (2 * i) * 16;
            const ulonglong2* w1 = WcombV + (2 * i + 1) * 16;
#pragma unroll
            for (int j = 0; j < 16; j++) {
                ulonglong2 wa = w0[j];
                fma2(a0, wa.x, h2[2 * j]); fma2(a0, wa.y, h2[2 * j + 1]);
                ulonglong2 wb = w1[j];
                fma2(a1, wb.x, h2[2 * j]); fma2(a1, wb.y, h2[2 * j + 1]);
            }
            float x0 = leaky(hadd2(a0) + sBcomb[2 * i]);
            float x1 = leaky(hadd2(a1) + sBcomb[2 * i + 1]);
            xp[i] = pack2(x0, x1);
        }
    }

    // ---- conf = softmax(h_final @ W_conf^T + b_conf) ----
    float lg[3];
#pragma unroll
    for (int r = 0; r < 3; r++) {
        u64 a = 0;
        const ulonglong2* w = WconfV + r * 16;
#pragma unroll
        for (int j = 0; j < 16; j++) {
            ulonglong2 wv = w[j];
            fma2(a, wv.x, h2[2 * j]); fma2(a, wv.y, h2[2 * j + 1]);
        }
        lg[r] = hadd2(a) + sm[OFF_BCONF + r];
    }
    float m = fmaxf(lg[0], fmaxf(lg[1], lg[2]));
    float e0 = __expf(lg[0] - m);
    float e1 = __expf(lg[1] - m);
    float e2 = __expf(lg[2] - m);
    float inv = __fdividef(1.f, e0 + e1 + e2);
    size_t confbase = (size_t)batch * (3 * SEQ_LEN * 2);
    out[confbase + (size_t)b * 3 + 0] = e0 * inv;
    out[confbase + (size_t)b * 3 + 1] = e1 * inv;
    out[confbase + (size_t)b * 3 + 2] = e2 * inv;
}

extern "C" void kernel_launch(void* const* d_in, const int* in_sizes, int n_in,
                              void* d_out, int out_size) {
    // metadata order: traj_abs, traj_rel, h0, c0, W_ih, W_hh, b_ih, b_hh,
    //                 W_se, b_se, W_h2p, b_h2p, W_conf, b_conf
    const float* traj_rel = (const float*)d_in[1];
    const float* h0   = (const float*)d_in[2];
    const float* c0   = (const float*)d_in[3];
    const float* W_ih = (const float*)d_in[4];
    const float* W_hh = (const float*)d_in[5];
    const float* b_ih = (const float*)d_in[6];
    const float* b_hh = (const float*)d_in[7];
    const float* W_se = (const float*)d_in[8];
    const float* b_se = (const float*)d_in[9];
    const float* W_h2p = (const float*)d_in[10];
    const float* b_h2p = (const float*)d_in[11];
    const float* W_conf = (const float*)d_in[12];
    const float* b_conf = (const float*)d_in[13];
    float* out = (float*)d_out;

    int batch = in_sizes[2] / HDIM;   // h0 element count / 64

    setup_kernel<<<1, 256>>>(W_se, b_se, W_h2p, b_h2p, b_ih, b_hh);

    cudaFuncSetAttribute(lstm_kernel, cudaFuncAttributeMaxDynamicSharedMemorySize, SMEM_BYTES);
    int grid = (batch + 127) / 128;
    lstm_kernel<<<grid, 128, SMEM_BYTES>>>(traj_rel, h0, c0, W_ih, W_hh,
                                           W_h2p, b_h2p, b_se, W_conf, b_conf,
                                           out, batch);
}

// round 5
// speedup vs baseline: 7.8163x; 7.8157x over previous
#include <cuda_runtime.h>
#include <cuda_fp16.h>
#include <cstdint>

#define SEQ_LEN 30
#define KPAD 88   // 176B row stride -> conflict-free fragment LDS (44g+2t mod 32 distinct)

// ---------------- precomputed weights (device globals) ----------------
__device__ __align__(16) __half gB1h[256 * KPAD];   // gates: [Whh | Wih], k-permuted fp16
__device__ __align__(16) __half gB2h[32 * KPAD];    // heads: [Wcomb | W_h2p | W_conf | 0]
__device__ __align__(16) float gBias1[256];         // b_ih + b_hh
__device__ __align__(16) float gBias2[32];          // [bcomb(16) | b_h2p(6) | b_conf(3) | 0]
__device__ float gWsex[16], gWsey[16], gBse[16];

// k-permutation within each 16-block: fragment quad {2t,2t+1,2t+8,2t+9} -> contiguous 4t..4t+3
__device__ __forceinline__ int kperm(int k) {
    int q = k & 15;
    return (k & ~15) + ((q & 7) >> 1) * 4 + ((q >> 3) << 1) + (q & 1);
}

__device__ __forceinline__ float sigf(float v)  { return __fdividef(1.f, 1.f + __expf(-v)); }
__device__ __forceinline__ float tanhx(float v) { return __fdividef(2.f, 1.f + __expf(-2.f * v)) - 1.f; }
__device__ __forceinline__ float leaky(float v) { return fmaxf(v, 0.f) + 0.01f * fminf(v, 0.f); }

__device__ __forceinline__ void fsplit(float v, __half& hi, __half& lo) {
    hi = __float2half_rn(v);
    lo = __float2half_rn(v - __half2float(hi));
}

// m16n8k16 fp16 MMA, fp32 accumulate (sm_80 PTX -> valid at plain sm_100 target)
__device__ __forceinline__ void mma4(float* d, const uint32_t* a, uint2 b) {
    asm volatile(
        "mma.sync.aligned.m16n8k16.row.col.f32.f16.f16.f32 "
        "{%0,%1,%2,%3}, {%4,%5,%6,%7}, {%8,%9}, {%0,%1,%2,%3};"
        : "+f"(d[0]), "+f"(d[1]), "+f"(d[2]), "+f"(d[3])
        : "r"(a[0]), "r"(a[1]), "r"(a[2]), "r"(a[3]), "r"(b.x), "r"(b.y));
}

// A fragment for rows {row, row+8}, k-tile kt, lane-quad t: two LDS.64
__device__ __forceinline__ void ldA4(uint32_t* f, const __half* sA, int row, int kt, int t) {
    uint2 v0 = *(const uint2*)(sA + row * KPAD + kt * 16 + 4 * t);
    uint2 v1 = *(const uint2*)(sA + (row + 8) * KPAD + kt * 16 + 4 * t);
    f[0] = v0.x; f[1] = v1.x; f[2] = v0.y; f[3] = v1.y;
}

// ============================================================================
__global__ void setup_kernel(const float* __restrict__ W_ih, const float* __restrict__ W_hh,
                             const float* __restrict__ b_ih, const float* __restrict__ b_hh,
                             const float* __restrict__ W_se, const float* __restrict__ b_se,
                             const float* __restrict__ W_h2p, const float* __restrict__ b_h2p,
                             const float* __restrict__ W_conf, const float* __restrict__ b_conf) {
    int t = threadIdx.x;
    // gates B1 [n=256][k=KPAD] = [W_hh | W_ih | pad]
    for (int idx = t; idx < 256 * KPAD; idx += 256) {
        int n = idx / KPAD, k = idx % KPAD;
        float v = 0.f;
        if (k < 64)      v = W_hh[n * 64 + k];
        else if (k < 80) v = W_ih[n * 16 + (k - 64)];
        int kk = (k < 80) ? kperm(k) : k;
        gB1h[n * KPAD + kk] = __float2half_rn(v);
    }
    // heads B2 [r=32][k=KPAD]; only k<64 used
    for (int idx = t; idx < 32 * KPAD; idx += 256) {
        int r = idx / KPAD, k = idx % KPAD;
        float v = 0.f;
        if (k < 64) {
            if (r < 16) {
                float s = 0.f;
#pragma unroll
                for (int p = 0; p < 6; p++) s += W_se[r * 6 + p] * W_h2p[p * 64 + k];
                v = s;
            } else if (r < 22) v = W_h2p[(r - 16) * 64 + k];
            else if (r < 25)   v = W_conf[(r - 22) * 64 + k];
        }
        int kk = (k < 80) ? kperm(k) : k;
        gB2h[r * KPAD + kk] = __float2half_rn(v);
    }
    if (t < 256) gBias1[t] = b_ih[t] + b_hh[t];
    if (t < 16) {
        float s = 0.f;
#pragma unroll
        for (int p = 0; p < 6; p++) s += W_se[t * 6 + p] * b_h2p[p];
        gBias2[t] = s + b_se[t];
        gWsex[t] = W_se[t * 6 + 0] + W_se[t * 6 + 2] + W_se[t * 6 + 4];
        gWsey[t] = W_se[t * 6 + 1] + W_se[t * 6 + 3] + W_se[t * 6 + 5];
        gBse[t] = b_se[t];
    } else if (t < 22) gBias2[t] = b_h2p[t - 16];
    else if (t < 25)   gBias2[t] = b_conf[t - 22];
    else if (t < 32)   gBias2[t] = 0.f;
}

// ============================================================================
// 256 threads = 8 warps; warp w owns batch rows [16w, 16w+16).
// After init, each lane reads exactly the A addresses it writes -> no in-loop barriers.
__global__ void __launch_bounds__(256, 1)
lstm_hmma_kernel(const float* __restrict__ traj_rel,
                 const float* __restrict__ h0, const float* __restrict__ c0,
                 float* __restrict__ out, int batch) {
    extern __shared__ char smem[];
    __half* sAh = (__half*)smem;                 // 128*KPAD fp16 (A hi)
    __half* sAl = sAh + 128 * KPAD;              // (A lo)
    __half* sB1 = sAl + 128 * KPAD;              // 256*KPAD
    __half* sB2 = sB1 + 256 * KPAD;              // 32*KPAD
    float* sBias1 = (float*)(sB2 + 32 * KPAD);
    float* sBias2 = sBias1 + 256;

    const int tid = threadIdx.x;
    const int w = tid >> 5, lane = tid & 31;
    const int g = lane >> 2, t = lane & 3;
    const int rowA = w * 16 + g;                 // fragment rows rowA, rowA+8
    const int bbase = blockIdx.x * 128;

    // ---- stage weights ----
    {
        const uint4* s1 = (const uint4*)gB1h;
        uint4* d1 = (uint4*)sB1;
        for (int i = tid; i < 256 * KPAD / 8; i += 256) d1[i] = s1[i];
        const uint4* s2 = (const uint4*)gB2h;
        uint4* d2 = (uint4*)sB2;
        for (int i = tid; i < 32 * KPAD / 8; i += 256) d2[i] = s2[i];
        if (tid < 256) sBias1[tid] = gBias1[tid];
        if (tid < 32)  sBias2[tid] = gBias2[tid];
    }

    // ---- init A: h0 (split) + x0 ----
    for (int idx = tid; idx < 128 * 64; idx += 256) {
        int row = idx >> 6, k = idx & 63;
        int b = bbase + row; if (b >= batch) b = batch - 1;
        float v = h0[(size_t)b * 64 + k];
        __half hi, lo; fsplit(v, hi, lo);
        int a = row * KPAD + kperm(k);
        sAh[a] = hi; sAl[a] = lo;
    }
    for (int idx = tid; idx < 128 * 16; idx += 256) {
        int row = idx >> 4, xk = idx & 15;
        int b = bbase + row; if (b >= batch) b = batch - 1;
        float tx = traj_rel[(size_t)b * 2 + 0];
        float ty = traj_rel[(size_t)b * 2 + 1];
        float v = leaky(tx * gWsex[xk] + ty * gWsey[xk] + gBse[xk]);
        __half hi, lo; fsplit(v, hi, lo);
        int a = row * KPAD + kperm(64 + xk);
        sAh[a] = hi; sAl[a] = lo;
    }

    // ---- c0 into fragment-aligned registers: c[R][2nt+j] = c0[row][8nt+2t+j] ----
    const int b0g = bbase + rowA;
    const int b1g = b0g + 8;
    const int b0c = (b0g < batch) ? b0g : batch - 1;
    const int b1c = (b1g < batch) ? b1g : batch - 1;
    float c[2][16];
#pragma unroll
    for (int nt = 0; nt < 8; nt++)
#pragma unroll
        for (int j = 0; j < 2; j++) {
            int k = 8 * nt + 2 * t + j;
            c[0][2 * nt + j] = c0[(size_t)b0c * 64 + k];
            c[1][2 * nt + j] = c0[(size_t)b1c * 64 + k];
        }

    float* o0 = out + (size_t)b0g * 180;
    float* o1 = out + (size_t)b1g * 180;

    __syncthreads();   // staging + A init visible; no further barriers needed

#pragma unroll 1
    for (int step = 0; step < SEQ_LEN; step++) {
        // ---- gates: D[128,256] = A @ B1^T  (+bias via init) ----
        float D[128];
#pragma unroll
        for (int nt = 0; nt < 32; nt++) {
            float2 bia = *(const float2*)(sBias1 + nt * 8 + 2 * t);
            D[nt * 4 + 0] = bia.x; D[nt * 4 + 1] = bia.y;
            D[nt * 4 + 2] = bia.x; D[nt * 4 + 3] = bia.y;
        }
#pragma unroll 1
        for (int kt = 0; kt < 5; kt++) {
            uint32_t Ah[4], Al[4];
            ldA4(Ah, sAh, rowA, kt, t);
            ldA4(Al, sAl, rowA, kt, t);
#pragma unroll
            for (int n4 = 0; n4 < 8; n4++) {
                uint2 bv0 = *(const uint2*)(sB1 + ((n4 * 4 + 0) * 8 + g) * KPAD + kt * 16 + 4 * t);
                uint2 bv1 = *(const uint2*)(sB1 + ((n4 * 4 + 1) * 8 + g) * KPAD + kt * 16 + 4 * t);
                uint2 bv2 = *(const uint2*)(sB1 + ((n4 * 4 + 2) * 8 + g) * KPAD + kt * 16 + 4 * t);
                uint2 bv3 = *(const uint2*)(sB1 + ((n4 * 4 + 3) * 8 + g) * KPAD + kt * 16 + 4 * t);
                mma4(D + (n4 * 4 + 0) * 4, Ah, bv0);
                mma4(D + (n4 * 4 + 1) * 4, Ah, bv1);
                mma4(D + (n4 * 4 + 2) * 4, Ah, bv2);
                mma4(D + (n4 * 4 + 3) * 4, Ah, bv3);
                mma4(D + (n4 * 4 + 0) * 4, Al, bv0);
                mma4(D + (n4 * 4 + 1) * 4, Al, bv1);
                mma4(D + (n4 * 4 + 2) * 4, Al, bv2);
                mma4(D + (n4 * 4 + 3) * 4, Al, bv3);
            }
        }

        // ---- LSTM pointwise + write h_t (split fp16) back into A ----
#pragma unroll
        for (int nt = 0; nt < 8; nt++) {
#pragma unroll
            for (int R = 0; R < 2; R++) {
                float hv[2];
#pragma unroll
                for (int j = 0; j < 2; j++) {
                    int di = R * 2 + j;
                    float gi = D[(0 * 8 + nt) * 4 + di];
                    float gf = D[(1 * 8 + nt) * 4 + di];
                    float gg = D[(2 * 8 + nt) * 4 + di];
                    float go = D[(3 * 8 + nt) * 4 + di];
                    float iv = sigf(gi), fv = sigf(gf);
                    float gv = tanhx(gg), ov = sigf(go);
                    float cc = fv * c[R][2 * nt + j] + iv * gv;
                    c[R][2 * nt + j] = cc;
                    hv[j] = ov * tanhx(cc);
                }
                __half h0h, h0l, h1h, h1l;
                fsplit(hv[0], h0h, h0l);
                fsplit(hv[1], h1h, h1l);
                int row = rowA + R * 8;
                int a = row * KPAD + (nt >> 1) * 16 + 4 * t + 2 * (nt & 1);  // kperm(8nt+2t)
                *(__half2*)(sAh + a) = __halves2half2(h0h, h1h);
                *(__half2*)(sAl + a) = __halves2half2(h0l, h1l);
            }
        }

        // ---- heads: D2[128,32] = A[:, :64] @ B2^T (+bias) ----
        float D2[16];
#pragma unroll
        for (int nt = 0; nt < 4; nt++) {
            float2 bia = *(const float2*)(sBias2 + nt * 8 + 2 * t);
            D2[nt * 4 + 0] = bia.x; D2[nt * 4 + 1] = bia.y;
            D2[nt * 4 + 2] = bia.x; D2[nt * 4 + 3] = bia.y;
        }
#pragma unroll 1
        for (int kt = 0; kt < 4; kt++) {
            uint32_t Ah[4], Al[4];
            ldA4(Ah, sAh, rowA, kt, t);
            ldA4(Al, sAl, rowA, kt, t);
            uint2 bv[4];
#pragma unroll
            for (int nt = 0; nt < 4; nt++)
                bv[nt] = *(const uint2*)(sB2 + (nt * 8 + g) * KPAD + kt * 16 + 4 * t);
#pragma unroll
            for (int nt = 0; nt < 4; nt++) mma4(D2 + nt * 4, Ah, bv[nt]);
#pragma unroll
            for (int nt = 0; nt < 4; nt++) mma4(D2 + nt * 4, Al, bv[nt]);
        }

        // ---- x_{t+1} = leaky(pre) -> A cols 64..79 (nt 0..1) ----
#pragma unroll
        for (int nt = 0; nt < 2; nt++) {
#pragma unroll
            for (int R = 0; R < 2; R++) {
                float x0 = leaky(D2[nt * 4 + R * 2 + 0]);
                float x1 = leaky(D2[nt * 4 + R * 2 + 1]);
                __half xh0, xl0, xh1, xl1;
                fsplit(x0, xh0, xl0);
                fsplit(x1, xh1, xl1);
                int row = rowA + R * 8;
                int a = row * KPAD + 64 + 4 * t + 2 * nt;   // kperm(64+8nt+2t)
                *(__half2*)(sAh + a) = __halves2half2(xh0, xh1);
                *(__half2*)(sAl + a) = __halves2half2(xl0, xl1);
            }
        }
        // ---- pred: rel = cols 16..21 (nt=2; t<3 -> sample s=t) ----
        if (t < 3) {
            if (b0g < batch)
                *(float2*)(o0 + t * 60 + step * 2) = make_float2(D2[8 + 0], D2[8 + 1]);
            if (b1g < batch)
                *(float2*)(o1 + t * 60 + step * 2) = make_float2(D2[8 + 2], D2[8 + 3]);
        }
        // ---- conf: logits at cols 22,23 (t==3, nt=2) and col 24 (t==0, nt=3) ----
        if (step == SEQ_LEN - 1) {
            float l2r0 = __shfl_sync(0xffffffffu, D2[12 + 0], lane & ~3, 32);
            float l2r1 = __shfl_sync(0xffffffffu, D2[12 + 2], lane & ~3, 32);
            if (t == 3) {
                float a0 = D2[8 + 0], a1 = D2[8 + 1], a2 = l2r0;
                float mx = fmaxf(a0, fmaxf(a1, a2));
                float e0 = __expf(a0 - mx), e1 = __expf(a1 - mx), e2 = __expf(a2 - mx);
                float inv = __fdividef(1.f, e0 + e1 + e2);
                if (b0g < batch) {
                    float* cf = out + (size_t)batch * 180 + (size_t)b0g * 3;
                    cf[0] = e0 * inv; cf[1] = e1 * inv; cf[2] = e2 * inv;
                }
                float c0_ = D2[8 + 2], c1_ = D2[8 + 3], c2_ = l2r1;
                float mx1 = fmaxf(c0_, fmaxf(c1_, c2_));
                float f0 = __expf(c0_ - mx1), f1 = __expf(c1_ - mx1), f2 = __expf(c2_ - mx1);
                float inv1 = __fdividef(1.f, f0 + f1 + f2);
                if (b1g < batch) {
                    float* cf = out + (size_t)batch * 180 + (size_t)b1g * 3;
                    cf[0] = f0 * inv1; cf[1] = f1 * inv1; cf[2] = f2 * inv1;
                }
            }
        }
    }
}

// ============================================================================
extern "C" void kernel_launch(void* const* d_in, const int* in_sizes, int n_in,
                              void* d_out, int out_size) {
    const float* traj_rel = (const float*)d_in[1];
    const float* h0   = (const float*)d_in[2];
    const float* c0   = (const float*)d_in[3];
    const float* W_ih = (const float*)d_in[4];
    const float* W_hh = (const float*)d_in[5];
    const float* b_ih = (const float*)d_in[6];
    const float* b_hh = (const float*)d_in[7];
    const float* W_se = (const float*)d_in[8];
    const float* b_se = (const float*)d_in[9];
    const float* W_h2p = (const float*)d_in[10];
    const float* b_h2p = (const float*)d_in[11];
    const float* W_conf = (const float*)d_in[12];
    const float* b_conf = (const float*)d_in[13];
    float* out = (float*)d_out;
    int batch = in_sizes[2] / 64;

    setup_kernel<<<1, 256>>>(W_ih, W_hh, b_ih, b_hh, W_se, b_se,
                             W_h2p, b_h2p, W_conf, b_conf);

    const int smem_bytes = (128 * KPAD * 2 + 256 * KPAD + 32 * KPAD) * 2 + 256 * 4 + 32 * 4;
    cudaFuncSetAttribute(lstm_hmma_kernel, cudaFuncAttributeMaxDynamicSharedMemorySize, smem_bytes);
    int grid = (batch + 127) / 128;
    lstm_hmma_kernel<<<grid, 256, smem_bytes>>>(traj_rel, h0, c0, out, batch);
}